// round 5
// baseline (speedup 1.0000x reference)
#include <cuda_runtime.h>
#include <math.h>

#define NROWS  131072
#define DDIM   128
#define KCODES 1024
#define BM     128
#define BK     128
#define PITCH  132
#define PITCH4 33
#define TAU    0.02f     // ambiguity margin (dist units); any fp32 scheme errs << this

__device__ float g_ET[KCODES * DDIM];   // [K][D] row-major (bitwise copies of E)
__device__ float g_see[KCODES];         // sum_d e^2 (fp32; exact repair makes order moot)
__device__ int   g_cnt;                 // ambiguous-row count
__device__ int   g_rows[NROWS];         // ambiguous row ids

// ---------------------------------------------------------------------------
__global__ void vq_prep_kernel(const float* __restrict__ E) {
    int tid    = blockIdx.x * blockDim.x + threadIdx.x;
    int stride = gridDim.x * blockDim.x;
    if (tid == 0) g_cnt = 0;            // reset per replay (prep runs first)

    for (int i = tid; i < KCODES * DDIM; i += stride) {
        int d = i / KCODES;
        int k = i - d * KCODES;
        g_ET[k * DDIM + d] = E[i];
    }
    for (int k = tid; k < KCODES; k += stride) {
        float s = 0.f;
        for (int d = 0; d < DDIM; d++) {
            float v = E[d * KCODES + k];
            s = __fmaf_rn(v, v, s);
        }
        g_see[k] = s;
    }
}

// ---------------------------------------------------------------------------
// Main: fp32 tile GEMM + top-2 argmin + gather; flags near-tie rows.
// Block: 256 threads as 16x16 (ty=rows, tx=codes), 8x8 micro-tile in 2x2
// quadrants; all smem accesses LDS.128 conflict-free.
// ---------------------------------------------------------------------------
__global__ void __launch_bounds__(256, 1)
vq_main_kernel(const float* __restrict__ X,
               const float* __restrict__ E,
               float* __restrict__ out) {
    extern __shared__ float smem[];
    float* Xs = smem;                       // [DDIM][PITCH] d-major
    float* Es = smem + DDIM * PITCH;        // [DDIM][PITCH]
    float* hs = Es + DDIM * PITCH;          // [BK]
    float* sxx_s = hs + BK;                 // [BM]
    int* bidx_s = (int*)(sxx_s + BM);       // [BM]

    const int tid = threadIdx.x;
    const int tx  = tid & 15;
    const int ty  = tid >> 4;
    const size_t base = (size_t)blockIdx.x * BM;

    for (int i = tid; i < BM * DDIM; i += 256) {
        int m = i >> 7;
        int d = i & 127;
        Xs[d * PITCH + m] = X[(base + m) * DDIM + d];
    }
    __syncthreads();

    if (tid < BM) {
        float s = 0.f;
        for (int d = 0; d < DDIM; d++) {
            float v = Xs[d * PITCH + tid];
            s = __fmaf_rn(v, v, s);
        }
        sxx_s[tid] = s;
    }
    __syncthreads();

    float sxx[8];
    #pragma unroll
    for (int i = 0; i < 8; i++) {
        int m = (i < 4) ? (ty * 4 + i) : (64 + ty * 4 + (i - 4));
        sxx[i] = sxx_s[m];
    }

    float bestd[8], secd[8];
    int   bidx[8];
    #pragma unroll
    for (int i = 0; i < 8; i++) { bestd[i] = INFINITY; secd[i] = INFINITY; bidx[i] = 0; }

    const float4* Eg4 = (const float4*)E;
    float4*       Es4w = (float4*)Es;
    const float4* Xs4 = (const float4*)Xs;
    const float4* Es4 = (const float4*)Es;

    for (int kb = 0; kb < KCODES; kb += BK) {
        __syncthreads();
        for (int i = tid; i < DDIM * (BK / 4); i += 256) {
            int d  = i >> 5;
            int k4 = i & 31;
            Es4w[d * PITCH4 + k4] = Eg4[d * (KCODES / 4) + (kb >> 2) + k4];
        }
        if (tid < BK) hs[tid] = g_see[kb + tid];
        __syncthreads();

        float acc[8][8];
        #pragma unroll
        for (int i = 0; i < 8; i++)
            #pragma unroll
            for (int j = 0; j < 8; j++) acc[i][j] = 0.f;

        #pragma unroll 4
        for (int d = 0; d < DDIM; d++) {
            float4 a0 = Xs4[d * PITCH4 + ty];
            float4 a1 = Xs4[d * PITCH4 + 16 + ty];
            float4 b0 = Es4[d * PITCH4 + tx];
            float4 b1 = Es4[d * PITCH4 + 16 + tx];
            float a[8] = {a0.x, a0.y, a0.z, a0.w, a1.x, a1.y, a1.z, a1.w};
            float b[8] = {b0.x, b0.y, b0.z, b0.w, b1.x, b1.y, b1.z, b1.w};
            #pragma unroll
            for (int i = 0; i < 8; i++)
                #pragma unroll
                for (int j = 0; j < 8; j++)
                    acc[i][j] = fmaf(a[i], b[j], acc[i][j]);
        }

        #pragma unroll
        for (int j = 0; j < 8; j++) {
            int kl = (j < 4) ? (tx * 4 + j) : (64 + tx * 4 + (j - 4));
            float see = hs[kl];
            int   kg = kb + kl;
            #pragma unroll
            for (int i = 0; i < 8; i++) {
                float dist = __fadd_rn(__fmaf_rn(-2.0f, acc[i][j], sxx[i]), see);
                if (dist < bestd[i]) {
                    secd[i] = bestd[i]; bestd[i] = dist; bidx[i] = kg;
                } else if (dist < secd[i]) {
                    secd[i] = dist;
                }
            }
        }
    }

    // Cross-lane top-2 reduction over the 16 tx lanes of each row.
    #pragma unroll
    for (int i = 0; i < 8; i++) {
        float b1 = bestd[i], b2 = secd[i];
        int   id = bidx[i];
        #pragma unroll
        for (int off = 1; off < 16; off <<= 1) {
            float b1o = __shfl_xor_sync(0xffffffffu, b1, off);
            float b2o = __shfl_xor_sync(0xffffffffu, b2, off);
            int   ido = __shfl_xor_sync(0xffffffffu, id, off);
            float nb2 = fminf(fmaxf(b1, b1o), fminf(b2, b2o));
            if (b1o < b1 || (b1o == b1 && ido < id)) { b1 = b1o; id = ido; }
            b2 = nb2;
        }
        if (tx == 0) {
            int m = (i < 4) ? (ty * 4 + i) : (64 + ty * 4 + (i - 4));
            bidx_s[m] = id;
            if (b2 - b1 < TAU) {                     // near-tie: exact repair later
                int pos = atomicAdd(&g_cnt, 1);
                g_rows[pos] = (int)(base + m);
            }
        }
    }
    __syncthreads();

    float4*       out4 = (float4*)out;
    const float4* ET4  = (const float4*)g_ET;
    for (int i = tid; i < BM * (DDIM / 4); i += 256) {
        int m = i >> 5;
        int v = i & 31;
        int id = bidx_s[m];
        out4[(base + m) * 32 + v] = ET4[id * 32 + v];
    }
}

// ---------------------------------------------------------------------------
// Repair: exact fp64 argmin over all K codes for flagged rows (ground truth).
// One block per flagged row (grid-stride). 128 threads x 8 codes each.
// ---------------------------------------------------------------------------
__global__ void __launch_bounds__(128, 4)
vq_repair_kernel(const float* __restrict__ X, float* __restrict__ out) {
    __shared__ float  xs[DDIM];
    __shared__ double rd[128];
    __shared__ int    ri[128];
    __shared__ int    widx_s;

    const int t = threadIdx.x;
    const int cnt = g_cnt;

    for (int r = blockIdx.x; r < cnt; r += gridDim.x) {
        const int row = g_rows[r];
        if (t < DDIM) xs[t] = X[(size_t)row * DDIM + t];
        __syncthreads();

        double bd = INFINITY;
        int    bi = 0;
        #pragma unroll
        for (int c = 0; c < 8; c++) {
            int k = t + 128 * c;
            const float* e = &g_ET[k * DDIM];
            double s = 0.0;
            #pragma unroll 8
            for (int d = 0; d < DDIM; d++) {
                double diff = (double)xs[d] - (double)e[d];
                s = fma(diff, diff, s);
            }
            if (s < bd || (s == bd && k < bi)) { bd = s; bi = k; }
        }
        rd[t] = bd; ri[t] = bi;
        __syncthreads();

        for (int off = 64; off > 0; off >>= 1) {
            if (t < off) {
                double od = rd[t + off]; int oi = ri[t + off];
                if (od < rd[t] || (od == rd[t] && oi < ri[t])) { rd[t] = od; ri[t] = oi; }
            }
            __syncthreads();
        }
        if (t == 0) widx_s = ri[0];
        __syncthreads();

        const int w = widx_s;
        if (t < DDIM) out[(size_t)row * DDIM + t] = g_ET[w * DDIM + t];
        __syncthreads();
    }
}

// ---------------------------------------------------------------------------
extern "C" void kernel_launch(void* const* d_in, const int* in_sizes, int n_in,
                              void* d_out, int out_size) {
    const float* X   = (const float*)d_in[0];   // [131072,128]
    const float* E   = (const float*)d_in[1];   // [128,1024]
    float*       out = (float*)d_out;

    vq_prep_kernel<<<64, 256>>>(E);

    const int smem_bytes = (2 * DDIM * PITCH + BK + BM) * (int)sizeof(float)
                         + BM * (int)sizeof(int);
    cudaFuncSetAttribute(vq_main_kernel,
                         cudaFuncAttributeMaxDynamicSharedMemorySize, smem_bytes);
    vq_main_kernel<<<NROWS / BM, 256, smem_bytes>>>(X, E, out);

    vq_repair_kernel<<<2048, 128>>>(X, out);
}